// round 16
// baseline (speedup 1.0000x reference)
#include <cuda_runtime.h>
#include <cstdint>

#define BATCH_ 16
#define SEQ_   2048
#define LIN_   256
#define MENC_  512
#define HD_    1024
#define FMLP_  4096
#define CH_    16
#define NCH_   128
#define ROWS_  (NCH_*BATCH_)        // 2048
#define APRON_ 1024
#define FROWS_ (APRON_ + ROWS_)     // 3072
#define PBLK_  192                  // persistent-kernel block count

// ---------- scratch (device globals; allocation is forbidden) ----------
__device__ float g_WE[(size_t)384*MENC_];
__device__ float g_WxB[(size_t)384*HD_];
__device__ float g_Bu[(size_t)BATCH_*SEQ_*HD_];
__device__ float g_D1[(size_t)16384*HD_];
__device__ float g_D2[(size_t)8192*HD_];
__device__ float g_P0[HD_*HD_];
__device__ float g_P1[HD_*HD_];
__device__ float g_P2[HD_*HD_];
__device__ float g_FA[(size_t)FROWS_*HD_];
__device__ float g_FB[(size_t)FROWS_*HD_];
__device__ float g_Z [BATCH_*HD_];
__device__ float g_HL[BATCH_*HD_];
__device__ float g_T [BATCH_*FMLP_];
__device__ unsigned g_ctr[32];

#define GF_BIAS   1
#define GF_SADD   2
#define GF_SSTORE 4
#define GF_ADDM   8

struct GA {
    const float* A; const float* B; float* C;
    const float* bias; const float* scanB; float* scanO; const float* addM;
    int lda, N, K, jstep, flags, addLd;
};

__host__ __device__ static inline GA mkGA(const float* A, int lda, const float* B, float* C,
                      int N, int K, int flags,
                      const float* bias = nullptr,
                      const float* scanB = nullptr, float* scanO = nullptr,
                      const float* addM = nullptr, int jstep = 0,
                      int addLd = HD_)
{
    GA g; g.A = A; g.B = B; g.C = C; g.bias = bias; g.scanB = scanB;
    g.scanO = scanO; g.addM = addM; g.lda = lda; g.N = N; g.K = K;
    g.jstep = jstep; g.flags = flags; g.addLd = addLd; return g;
}

__device__ __forceinline__ uint32_t s2u(const void* p){
    uint32_t a; asm("{ .reg .u64 t; cvta.to.shared.u64 t,%1; cvt.u32.u64 %0,t; }" : "=r"(a) : "l"(p));
    return a;
}
__device__ __forceinline__ void cpasync16(uint32_t dst, const float* src){
    asm volatile("cp.async.cg.shared.global [%0],[%1],16;" :: "r"(dst), "l"(src));
}
#define CP_COMMIT() asm volatile("cp.async.commit_group;" ::: "memory")
#define CP_WAIT0()  asm volatile("cp.async.wait_group 0;" ::: "memory")
__device__ __forceinline__ float4 ldgcg4(const float* p){
    float4 v;
    asm volatile("ld.global.cg.v4.f32 {%0,%1,%2,%3},[%4];"
                 : "=f"(v.x),"=f"(v.y),"=f"(v.z),"=f"(v.w) : "l"(p));
    return v;
}

// 128x128 tile, 256 threads, 8x8 micro-tile, packed f32x2 FMA.
// A: register-staged transpose (ld.global.cg); B: cp.async double-buffered,
// one __syncthreads per 16-k panel. Cross-barrier-safe: all global reads of
// potentially-rewritten data go through L2 (cg / cp.async.cg).
__device__ __forceinline__ void gemm_core(const GA& g,
                                          float (&As)[2][16][132],
                                          float (&Bs)[2][16][132],
                                          int bxi, int byi)
{
    const int tid = threadIdx.x;
    const int tm = tid >> 4, tn = tid & 15;
    const int m0 = byi * 128, n0 = bxi * 128;
    const int lar = tid >> 1, lac = (tid & 1) * 8;
    const int N = g.N, K = g.K;

    const float* Aload = g.A + (size_t)(m0 + lar) * g.lda + lac;
    const float* Bload = g.B + n0;
    const uint32_t bsU = s2u(&Bs[0][0][0]);
    const int br = tid >> 5, bc = (tid & 31) * 4;

    unsigned long long acc[4][8];
#pragma unroll
    for (int p = 0; p < 4; p++)
#pragma unroll
        for (int q = 0; q < 8; q++) acc[p][q] = 0ull;

    {
        cpasync16(bsU + ((br * 132 + bc) << 2),       Bload + (size_t)br * N + bc);
        cpasync16(bsU + (((br + 8) * 132 + bc) << 2), Bload + (size_t)(br + 8) * N + bc);
        CP_COMMIT();
        float4 a0 = ldgcg4(Aload);
        float4 a1 = ldgcg4(Aload + 4);
        As[0][lac+0][lar]=a0.x; As[0][lac+1][lar]=a0.y; As[0][lac+2][lar]=a0.z; As[0][lac+3][lar]=a0.w;
        As[0][lac+4][lar]=a1.x; As[0][lac+5][lar]=a1.y; As[0][lac+6][lar]=a1.z; As[0][lac+7][lar]=a1.w;
    }

    int buf = 0;
    for (int kt = 0; kt < K; kt += 16) {
        const bool more = (kt + 16) < K;
        CP_WAIT0();
        __syncthreads();
        if (more) {
            const float* Bk = Bload + (size_t)(kt + 16) * N;
            const uint32_t bb = bsU + (uint32_t)((buf ^ 1) * 16 * 132 * 4);
            cpasync16(bb + ((br * 132 + bc) << 2),       Bk + (size_t)br * N + bc);
            cpasync16(bb + (((br + 8) * 132 + bc) << 2), Bk + (size_t)(br + 8) * N + bc);
            CP_COMMIT();
        }
        float4 a0, a1;
        if (more) {
            a0 = ldgcg4(Aload + kt + 16);
            a1 = ldgcg4(Aload + kt + 20);
        }
#pragma unroll
        for (int k = 0; k < 16; k++) {
            const ulonglong2 pa0 = *(const ulonglong2*)&As[buf][k][tm * 8];
            const ulonglong2 pa1 = *(const ulonglong2*)&As[buf][k][tm * 8 + 4];
            const float4 x = *(const float4*)&Bs[buf][k][tn * 8];
            const float4 y = *(const float4*)&Bs[buf][k][tn * 8 + 4];
            unsigned long long pb[8];
            asm("mov.b64 %0,{%1,%1};" : "=l"(pb[0]) : "f"(x.x));
            asm("mov.b64 %0,{%1,%1};" : "=l"(pb[1]) : "f"(x.y));
            asm("mov.b64 %0,{%1,%1};" : "=l"(pb[2]) : "f"(x.z));
            asm("mov.b64 %0,{%1,%1};" : "=l"(pb[3]) : "f"(x.w));
            asm("mov.b64 %0,{%1,%1};" : "=l"(pb[4]) : "f"(y.x));
            asm("mov.b64 %0,{%1,%1};" : "=l"(pb[5]) : "f"(y.y));
            asm("mov.b64 %0,{%1,%1};" : "=l"(pb[6]) : "f"(y.z));
            asm("mov.b64 %0,{%1,%1};" : "=l"(pb[7]) : "f"(y.w));
#pragma unroll
            for (int q = 0; q < 8; q++) {
                asm("fma.rn.f32x2 %0,%1,%2,%0;" : "+l"(acc[0][q]) : "l"(pa0.x), "l"(pb[q]));
                asm("fma.rn.f32x2 %0,%1,%2,%0;" : "+l"(acc[1][q]) : "l"(pa0.y), "l"(pb[q]));
                asm("fma.rn.f32x2 %0,%1,%2,%0;" : "+l"(acc[2][q]) : "l"(pa1.x), "l"(pb[q]));
                asm("fma.rn.f32x2 %0,%1,%2,%0;" : "+l"(acc[3][q]) : "l"(pa1.y), "l"(pb[q]));
            }
        }
        if (more) {
            const int nb = buf ^ 1;
            As[nb][lac+0][lar]=a0.x; As[nb][lac+1][lar]=a0.y; As[nb][lac+2][lar]=a0.z; As[nb][lac+3][lar]=a0.w;
            As[nb][lac+4][lar]=a1.x; As[nb][lac+5][lar]=a1.y; As[nb][lac+6][lar]=a1.z; As[nb][lac+7][lar]=a1.w;
        }
        buf ^= 1;
    }

    float cv[8][8];
#pragma unroll
    for (int p = 0; p < 4; p++)
#pragma unroll
        for (int q = 0; q < 8; q++)
            asm("mov.b64 {%0,%1},%2;"
                : "=f"(cv[2*p][q]), "=f"(cv[2*p+1][q]) : "l"(acc[p][q]));

    const int F = g.flags;
    const int gc = n0 + tn * 8;
    float4 bv0 = make_float4(0.f,0.f,0.f,0.f), bv1 = bv0;
    if (F & GF_BIAS) {
        bv0 = *(const float4*)(g.bias + gc);
        bv1 = *(const float4*)(g.bias + gc + 4);
    }
#pragma unroll
    for (int mr = 0; mr < 8; mr++) {
        const int gm = m0 + tm * 8 + mr;
        float4 v0 = make_float4(cv[mr][0], cv[mr][1], cv[mr][2], cv[mr][3]);
        float4 v1 = make_float4(cv[mr][4], cv[mr][5], cv[mr][6], cv[mr][7]);
        if (F & GF_BIAS) {
            v0.x += bv0.x; v0.y += bv0.y; v0.z += bv0.z; v0.w += bv0.w;
            v1.x += bv1.x; v1.y += bv1.y; v1.z += bv1.z; v1.w += bv1.w;
        }
        if (F & GF_ADDM) {
            const float* ap = g.addM + (size_t)gm * g.addLd + gc;
            float4 u0 = ldgcg4(ap);
            float4 u1 = ldgcg4(ap + 4);
            v0.x += u0.x; v0.y += u0.y; v0.z += u0.z; v0.w += u0.w;
            v1.x += u1.x; v1.y += u1.y; v1.z += u1.z; v1.w += u1.w;
        }
        size_t soff = 0;
        if (F & (GF_SADD | GF_SSTORE))
            soff = ((size_t)(gm & 15) * SEQ_ + (size_t)(gm >> 4) * CH_ + g.jstep) * HD_ + gc;
        if (F & GF_SADD) {
            float4 s0 = ldgcg4(g.scanB + soff);
            float4 s1 = ldgcg4(g.scanB + soff + 4);
            v0.x += s0.x; v0.y += s0.y; v0.z += s0.z; v0.w += s0.w;
            v1.x += s1.x; v1.y += s1.y; v1.z += s1.z; v1.w += s1.w;
        }
        *(float4*)(g.C + (size_t)gm * N + gc)     = v0;
        *(float4*)(g.C + (size_t)gm * N + gc + 4) = v1;
        if (F & GF_SSTORE) {
            *(float4*)(g.scanO + soff)     = v0;
            *(float4*)(g.scanO + soff + 4) = v1;
        }
    }
}

__global__ void __launch_bounds__(256, 2) gemm_one(GA g)
{
    __shared__ float As[2][16][132];
    __shared__ float Bs[2][16][132];
    gemm_core(g, As, Bs, blockIdx.x, blockIdx.y);
}

__global__ void __launch_bounds__(256, 2) gemm_two(GA g1, GA g2, int bySplit)
{
    __shared__ float As[2][16][132];
    __shared__ float Bs[2][16][132];
    if ((int)blockIdx.y < bySplit)
        gemm_core(g1, As, Bs, blockIdx.x, blockIdx.y);
    else
        gemm_core(g2, As, Bs, blockIdx.x, blockIdx.y - bySplit);
}

// grid barrier: release (fence + atomic arrive) / acquire (volatile spin)
__device__ __forceinline__ void gbar(int s)
{
    __syncthreads();
    __threadfence();
    if (threadIdx.x == 0) {
        atomicAdd(&g_ctr[s], 1u);
        while (*(volatile unsigned*)&g_ctr[s] < (unsigned)PBLK_) {}
    }
    __syncthreads();
}

// Persistent serial mid-section: apron zero -> endpoint remap -> 7 prefix
// rounds (squaring fused on blocks 128..191) -> 16 phase-2 scan steps.
// MUST launch with exactly PBLK_ blocks (all co-resident: occ 2, 33.8KB smem).
__global__ void __launch_bounds__(256, 2)
persist(float* FA, float* FB, const float* Amat,
        float* Pk0, float* Po0,
        const float* Bu, const float* D2, float* outH)
{
    __shared__ float As[2][16][132];
    __shared__ float Bs[2][16][132];
    const size_t AP = (size_t)APRON_ * HD_;
    const int bid = blockIdx.x;
    int step = 0;

    // step A: zero both aprons (2 x 1024 rows x 1024 floats)
    {
        float4* fa = (float4*)FA;
        float4* fb = (float4*)FB;
        const size_t n4 = (size_t)APRON_ * HD_ / 4;
        for (size_t i = (size_t)bid * 256 + threadIdx.x; i < n4;
             i += (size_t)PBLK_ * 256) {
            fa[i] = make_float4(0.f, 0.f, 0.f, 0.f);
            fb[i] = make_float4(0.f, 0.f, 0.f, 0.f);
        }
    }
    gbar(step++);

    // step B: remap batch-major endpoints (row b*128+c) -> FA+AP (row c*16+b)
    for (int r = bid; r < ROWS_; r += PBLK_) {
        const int b = r >> 7, c = r & 127;
        ((float4*)(FA + AP + (size_t)(c * 16 + b) * HD_))[threadIdx.x] =
            ldgcg4(D2 + (size_t)r * HD_ + threadIdx.x * 4);
    }
    gbar(step++);

    // 7 Hillis-Steele prefix rounds, squaring P between rounds
    float* cur = FA; float* nxt = FB;
    float* Pk = Pk0; float* Po = Po0;
    for (int r = 0; r < 7; r++) {
        const int s = 1 << r;
        if (bid < 128) {
            GA pre = mkGA(cur + AP - (size_t)16 * s * HD_, HD_, Pk, nxt + AP,
                          HD_, HD_, GF_ADDM, nullptr, nullptr, nullptr, cur + AP);
            gemm_core(pre, As, Bs, bid & 7, bid >> 3);
        } else if (r < 6) {
            const int b2 = bid - 128;
            if (b2 < 64) {
                GA sq = mkGA(Pk, HD_, Pk, Po, HD_, HD_, 0);
                gemm_core(sq, As, Bs, b2 & 7, b2 >> 3);
            }
        }
        gbar(step++);
        float* t = cur; cur = nxt; nxt = t;
        if (r < 6) { float* u = Pk; Pk = Po; Po = u; }
    }

    // 16 phase-2 scan steps (exclusive prefix on step 0)
    for (int j = 0; j < CH_; j++) {
        if (bid < 128) {
            const float* Ain = (j == 0) ? (cur + AP - (size_t)16 * HD_) : (cur + AP);
            GA g = mkGA(Ain, HD_, Amat, nxt + AP, HD_, HD_, GF_SADD | GF_SSTORE,
                        nullptr, Bu, outH, nullptr, j);
            gemm_core(g, As, Bs, bid & 7, bid >> 3);
        }
        if (j < CH_ - 1) gbar(step++);
        float* t = cur; cur = nxt; nxt = t;
    }
}

__global__ void zeroCtr()
{
    if (threadIdx.x < 32) g_ctr[threadIdx.x] = 0u;
}

#define SF_BIAS 1
#define SF_RELU 2
#define SF_ADD  4

// Small-M (<=16) GEMM with 4-way k-split, deterministic smem reduction.
template<int F>
__global__ void __launch_bounds__(256)
sgemmKS(const float* __restrict__ Ap, long lda,
        const float* __restrict__ Bp, int ldb,
        float* __restrict__ Cp, int ldc,
        const float* __restrict__ bias,
        const float* __restrict__ addend, long ldadd,
        int M, int K)
{
    __shared__ float As[4][16][33];
    __shared__ float Rs[4][16][64];
    const int tid = threadIdx.x;
    const int c = tid & 63, g = tid >> 6;
    const int col = blockIdx.x * 64 + c;
    const int kQ = K >> 2;
    float acc[16];
#pragma unroll
    for (int r = 0; r < 16; r++) acc[r] = 0.f;
    for (int k0 = 0; k0 < kQ; k0 += 32) {
        __syncthreads();
        for (int e = tid; e < 2048; e += 256) {
            const int gg = e >> 9, rem = e & 511, r = rem >> 5, kk = rem & 31;
            As[gg][r][kk] = (r < M) ? Ap[(size_t)r * lda + gg * kQ + k0 + kk] : 0.f;
        }
        __syncthreads();
#pragma unroll 8
        for (int kk = 0; kk < 32; kk++) {
            const float bv = Bp[(size_t)(g * kQ + k0 + kk) * ldb + col];
#pragma unroll
            for (int r = 0; r < 16; r++) acc[r] += As[g][r][kk] * bv;
        }
    }
    __syncthreads();
#pragma unroll
    for (int r = 0; r < 16; r++) Rs[g][r][c] = acc[r];
    __syncthreads();
    if (g == 0) {
#pragma unroll
        for (int r = 0; r < 16; r++) {
            if (r < M) {
                float v = Rs[0][r][c] + Rs[1][r][c] + Rs[2][r][c] + Rs[3][r][c];
                if (F & SF_BIAS) v += bias[col];
                if (F & SF_ADD)  v += addend[(size_t)r * ldadd + col];
                if (F & SF_RELU) v = fmaxf(v, 0.f);
                Cp[(size_t)r * ldc + col] = v;
            }
        }
    }
}

__global__ void __launch_bounds__(256)
ln16(const float* __restrict__ z, const float* __restrict__ gam,
     const float* __restrict__ bet, float* __restrict__ o)
{
    __shared__ float s1[8], s2[8];
    const int b = blockIdx.x, tid = threadIdx.x;
    float4 v = ((const float4*)(z + (size_t)b * HD_))[tid];
    float s = v.x + v.y + v.z + v.w;
    float q = v.x*v.x + v.y*v.y + v.z*v.z + v.w*v.w;
    for (int d = 16; d > 0; d >>= 1) {
        s += __shfl_xor_sync(0xffffffffu, s, d);
        q += __shfl_xor_sync(0xffffffffu, q, d);
    }
    if ((tid & 31) == 0) { s1[tid >> 5] = s; s2[tid >> 5] = q; }
    __syncthreads();
    if (tid < 8) {
        s = s1[tid]; q = s2[tid];
        for (int d = 4; d > 0; d >>= 1) {
            s += __shfl_xor_sync(0xffu, s, d);
            q += __shfl_xor_sync(0xffu, q, d);
        }
        if (tid == 0) { s1[0] = s; s2[0] = q; }
    }
    __syncthreads();
    const float mu = s1[0] * (1.f / HD_);
    const float var = s2[0] * (1.f / HD_) - mu * mu;
    const float rs = rsqrtf(var + 1e-5f);
    float4 gg = ((const float4*)gam)[tid];
    float4 bb = ((const float4*)bet)[tid];
    float4 r;
    r.x = (v.x - mu) * rs * gg.x + bb.x;
    r.y = (v.y - mu) * rs * gg.y + bb.y;
    r.z = (v.z - mu) * rs * gg.z + bb.z;
    r.w = (v.w - mu) * rs * gg.w + bb.w;
    ((float4*)(o + (size_t)b * HD_))[tid] = r;
}

// stage [Wenc(256 rows); benc(1); zeros(127)] into a 384x512 buffer
__global__ void stageWE(const float* __restrict__ Wenc,
                        const float* __restrict__ benc, float* __restrict__ S)
{
    const int r = blockIdx.x, i = threadIdx.x;
    float2 v = make_float2(0.f, 0.f);
    if (r < 256)       v = ((const float2*)(Wenc + (size_t)r * MENC_))[i];
    else if (r == 256) v = ((const float2*)benc)[i];
    ((float2*)(S + (size_t)r * MENC_))[i] = v;
}

extern "C" void kernel_launch(void* const* d_in, const int* in_sizes, int n_in,
                              void* d_out, int out_size)
{
    (void)in_sizes; (void)n_in; (void)out_size;
    const float* x    = (const float*)d_in[0];
    const float* Wenc = (const float*)d_in[1];
    const float* benc = (const float*)d_in[2];
    const float* WB   = (const float*)d_in[3];
    const float* Amat = (const float*)d_in[4];
    const float* Wres = (const float*)d_in[5];
    const float* bres = (const float*)d_in[6];
    const float* lng  = (const float*)d_in[7];
    const float* lnb  = (const float*)d_in[8];
    const float* W1   = (const float*)d_in[9];
    const float* b1   = (const float*)d_in[10];
    const float* W2   = (const float*)d_in[11];
    const float* b2   = (const float*)d_in[12];
    float* out0 = (float*)d_out;                 // (16,1024) MLP head
    float* outH = out0 + BATCH_ * HD_;           // (16,2048,1024) H_seq_pre

    float *WE, *WxB, *Bu, *D1, *D2, *P0, *P1, *P2, *FA, *FB, *Z, *HL, *T;
    cudaGetSymbolAddress((void**)&WE,   g_WE);
    cudaGetSymbolAddress((void**)&WxB,  g_WxB);
    cudaGetSymbolAddress((void**)&Bu,   g_Bu);
    cudaGetSymbolAddress((void**)&D1,   g_D1);
    cudaGetSymbolAddress((void**)&D2,   g_D2);
    cudaGetSymbolAddress((void**)&P0,   g_P0);
    cudaGetSymbolAddress((void**)&P1,   g_P1);
    cudaGetSymbolAddress((void**)&P2,   g_P2);
    cudaGetSymbolAddress((void**)&FA,   g_FA);
    cudaGetSymbolAddress((void**)&FB,   g_FB);
    cudaGetSymbolAddress((void**)&Z,    g_Z);
    cudaGetSymbolAddress((void**)&HL,   g_HL);
    cudaGetSymbolAddress((void**)&T,    g_T);

    // 0) barrier counters + encoder staging
    zeroCtr<<<1, 32>>>();
    stageWE<<<384, 256>>>(Wenc, benc, WE);

    // 1) [Wx; bvec] = [Wenc; benc] @ WB
    gemm_one<<<dim3(8, 3), 256>>>(mkGA(WE, MENC_, WB, WxB, HD_, MENC_, 0));

    // 2) Bu = x2d @ Wx + bvec   (32768 x 1024, K=256)
    gemm_one<<<dim3(8, 256), 256>>>(mkGA(x, LIN_, WxB, Bu, HD_, LIN_, GF_BIAS,
                                         WxB + (size_t)256 * HD_));

    // 3) Phase 1 by pairwise doubling (4 serial levels), squarings fused
    gemm_two<<<dim3(8, 136), 256>>>(
        mkGA(Bu, 2*HD_, Amat, D1, HD_, HD_, GF_ADDM, nullptr, nullptr, nullptr,
             Bu + HD_, 0, 2*HD_),
        mkGA(Amat, HD_, Amat, P0, HD_, HD_, 0), 128);
    gemm_two<<<dim3(8, 72), 256>>>(
        mkGA(D1, 2*HD_, P0, D2, HD_, HD_, GF_ADDM, nullptr, nullptr, nullptr,
             D1 + HD_, 0, 2*HD_),
        mkGA(P0, HD_, P0, P1, HD_, HD_, 0), 64);
    gemm_two<<<dim3(8, 40), 256>>>(
        mkGA(D2, 2*HD_, P1, D1, HD_, HD_, GF_ADDM, nullptr, nullptr, nullptr,
             D2 + HD_, 0, 2*HD_),
        mkGA(P1, HD_, P1, P2, HD_, HD_, 0), 32);
    gemm_two<<<dim3(8, 24), 256>>>(
        mkGA(D1, 2*HD_, P2, D2, HD_, HD_, GF_ADDM, nullptr, nullptr, nullptr,
             D1 + HD_, 0, 2*HD_),
        mkGA(P2, HD_, P2, P0, HD_, HD_, 0), 16);
    // D2 = chunk endpoints (batch-major); P0 = A^16

    // 4+5) persistent: aprons + remap + 7 prefix rounds + 16 phase-2 steps
    persist<<<PBLK_, 256>>>(FA, FB, Amat, P0, P1, Bu, D2, outH);

    // 6) z = x[:, -1, :] @ W_res + b_res + H_seq_pre[:, -1, :]
    sgemmKS<SF_BIAS | SF_ADD><<<16, 256>>>(x + (size_t)(SEQ_ - 1) * LIN_,
                                           (long)SEQ_ * LIN_,
                                           Wres, HD_, Z, HD_, bres,
                                           outH + (size_t)(SEQ_ - 1) * HD_,
                                           (long)SEQ_ * HD_, BATCH_, LIN_);
    // 7) LayerNorm
    ln16<<<BATCH_, 256>>>(Z, lng, lnb, HL);
    // 8) MLP head
    sgemmKS<SF_BIAS | SF_RELU><<<FMLP_ / 64, 256>>>(HL, HD_, W1, FMLP_, T, FMLP_,
                                                    b1, nullptr, 0, BATCH_, HD_);
    sgemmKS<SF_BIAS><<<HD_ / 64, 256>>>(T, FMLP_, W2, HD_, out0, HD_,
                                        b2, nullptr, 0, BATCH_, FMLP_);
}

// round 17
// speedup vs baseline: 1.0526x; 1.0526x over previous
#include <cuda_runtime.h>
#include <cstdint>

#define BATCH_ 16
#define SEQ_   2048
#define LIN_   256
#define MENC_  512
#define HD_    1024
#define FMLP_  4096
#define CH_    16
#define NCH_   128
#define ROWS_  (NCH_*BATCH_)        // 2048
#define APRON_ 1024
#define FROWS_ (APRON_ + ROWS_)     // 3072
#define PBLK_  256                  // persistent phase-2 block count (n64 tiles)

// ---------- scratch (device globals; allocation is forbidden) ----------
__device__ float g_WE[(size_t)384*MENC_];
__device__ float g_WxB[(size_t)384*HD_];
__device__ float g_Bu[(size_t)BATCH_*SEQ_*HD_];
__device__ float g_D1[(size_t)16384*HD_];
__device__ float g_D2[(size_t)8192*HD_];
__device__ float g_P0[HD_*HD_];
__device__ float g_P1[HD_*HD_];
__device__ float g_P2[HD_*HD_];
__device__ float g_FA[(size_t)FROWS_*HD_];
__device__ float g_FB[(size_t)FROWS_*HD_];
__device__ float g_Z [BATCH_*HD_];
__device__ float g_HL[BATCH_*HD_];
__device__ float g_T [BATCH_*FMLP_];
__device__ unsigned g_ctr[32];

#define GF_BIAS   1
#define GF_SADD   2
#define GF_SSTORE 4
#define GF_ADDM   8

struct GA {
    const float* A; const float* B; float* C;
    const float* bias; const float* scanB; float* scanO; const float* addM;
    int lda, N, K, jstep, flags, addLd;
};

__host__ __device__ static inline GA mkGA(const float* A, int lda, const float* B, float* C,
                      int N, int K, int flags,
                      const float* bias = nullptr,
                      const float* scanB = nullptr, float* scanO = nullptr,
                      const float* addM = nullptr, int jstep = 0,
                      int addLd = HD_)
{
    GA g; g.A = A; g.B = B; g.C = C; g.bias = bias; g.scanB = scanB;
    g.scanO = scanO; g.addM = addM; g.lda = lda; g.N = N; g.K = K;
    g.jstep = jstep; g.flags = flags; g.addLd = addLd; return g;
}

__device__ __forceinline__ uint32_t s2u(const void* p){
    uint32_t a; asm("{ .reg .u64 t; cvta.to.shared.u64 t,%1; cvt.u32.u64 %0,t; }" : "=r"(a) : "l"(p));
    return a;
}
__device__ __forceinline__ void cpasync16(uint32_t dst, const float* src){
    asm volatile("cp.async.cg.shared.global [%0],[%1],16;" :: "r"(dst), "l"(src));
}
#define CP_COMMIT() asm volatile("cp.async.commit_group;" ::: "memory")
#define CP_WAIT0()  asm volatile("cp.async.wait_group 0;" ::: "memory")
__device__ __forceinline__ float4 ldgcg4(const float* p){
    float4 v;
    asm volatile("ld.global.cg.v4.f32 {%0,%1,%2,%3},[%4];"
                 : "=f"(v.x),"=f"(v.y),"=f"(v.z),"=f"(v.w) : "l"(p));
    return v;
}

// ---------------- shared epilogue ----------------
__device__ __forceinline__ void epi_row(const GA& g, int gm, int gc, int nw,
                                        const float* v)
{
    const int F = g.flags;
    float buf[8];
#pragma unroll
    for (int q = 0; q < 8; q++) buf[q] = (q < nw) ? v[q] : 0.f;
    if (F & GF_BIAS)
        for (int q = 0; q < nw; q++) buf[q] += g.bias[gc + q];
    if (F & GF_ADDM) {
        const float* ap = g.addM + (size_t)gm * g.addLd + gc;
        for (int q = 0; q < nw; q++) buf[q] += ap[q];
    }
    size_t soff = 0;
    if (F & (GF_SADD | GF_SSTORE))
        soff = ((size_t)(gm & 15) * SEQ_ + (size_t)(gm >> 4) * CH_ + g.jstep) * HD_ + gc;
    if (F & GF_SADD) {
        const float* sp = g.scanB + soff;
        for (int q = 0; q < nw; q++) buf[q] += sp[q];
    }
    float* cp = g.C + (size_t)gm * g.N + gc;
    for (int q = 0; q < nw; q += 4)
        *(float4*)(cp + q) = make_float4(buf[q], buf[q+1], buf[q+2], buf[q+3]);
    if (F & GF_SSTORE) {
        float* op = g.scanO + soff;
        for (int q = 0; q < nw; q += 4)
            *(float4*)(op + q) = make_float4(buf[q], buf[q+1], buf[q+2], buf[q+3]);
    }
}

// ---------------- 128x128 core (throughput launches) ----------------
__device__ __forceinline__ void gemm_core(const GA& g,
                                          float (&As)[2][16][132],
                                          float (&Bs)[2][16][132],
                                          int bxi, int byi)
{
    const int tid = threadIdx.x;
    const int tm = tid >> 4, tn = tid & 15;
    const int m0 = byi * 128, n0 = bxi * 128;
    const int lar = tid >> 1, lac = (tid & 1) * 8;
    const int N = g.N, K = g.K;

    const float* Aload = g.A + (size_t)(m0 + lar) * g.lda + lac;
    const float* Bload = g.B + n0;
    const uint32_t bsU = s2u(&Bs[0][0][0]);
    const int br = tid >> 5, bc = (tid & 31) * 4;

    unsigned long long acc[4][8];
#pragma unroll
    for (int p = 0; p < 4; p++)
#pragma unroll
        for (int q = 0; q < 8; q++) acc[p][q] = 0ull;

    {
        cpasync16(bsU + ((br * 132 + bc) << 2),       Bload + (size_t)br * N + bc);
        cpasync16(bsU + (((br + 8) * 132 + bc) << 2), Bload + (size_t)(br + 8) * N + bc);
        CP_COMMIT();
        float4 a0 = ldgcg4(Aload);
        float4 a1 = ldgcg4(Aload + 4);
        As[0][lac+0][lar]=a0.x; As[0][lac+1][lar]=a0.y; As[0][lac+2][lar]=a0.z; As[0][lac+3][lar]=a0.w;
        As[0][lac+4][lar]=a1.x; As[0][lac+5][lar]=a1.y; As[0][lac+6][lar]=a1.z; As[0][lac+7][lar]=a1.w;
    }

    int buf = 0;
    for (int kt = 0; kt < K; kt += 16) {
        const bool more = (kt + 16) < K;
        CP_WAIT0();
        __syncthreads();
        if (more) {
            const float* Bk = Bload + (size_t)(kt + 16) * N;
            const uint32_t bb = bsU + (uint32_t)((buf ^ 1) * 16 * 132 * 4);
            cpasync16(bb + ((br * 132 + bc) << 2),       Bk + (size_t)br * N + bc);
            cpasync16(bb + (((br + 8) * 132 + bc) << 2), Bk + (size_t)(br + 8) * N + bc);
            CP_COMMIT();
        }
        float4 a0, a1;
        if (more) {
            a0 = ldgcg4(Aload + kt + 16);
            a1 = ldgcg4(Aload + kt + 20);
        }
#pragma unroll
        for (int k = 0; k < 16; k++) {
            const ulonglong2 pa0 = *(const ulonglong2*)&As[buf][k][tm * 8];
            const ulonglong2 pa1 = *(const ulonglong2*)&As[buf][k][tm * 8 + 4];
            const float4 x = *(const float4*)&Bs[buf][k][tn * 8];
            const float4 y = *(const float4*)&Bs[buf][k][tn * 8 + 4];
            unsigned long long pb[8];
            asm("mov.b64 %0,{%1,%1};" : "=l"(pb[0]) : "f"(x.x));
            asm("mov.b64 %0,{%1,%1};" : "=l"(pb[1]) : "f"(x.y));
            asm("mov.b64 %0,{%1,%1};" : "=l"(pb[2]) : "f"(x.z));
            asm("mov.b64 %0,{%1,%1};" : "=l"(pb[3]) : "f"(x.w));
            asm("mov.b64 %0,{%1,%1};" : "=l"(pb[4]) : "f"(y.x));
            asm("mov.b64 %0,{%1,%1};" : "=l"(pb[5]) : "f"(y.y));
            asm("mov.b64 %0,{%1,%1};" : "=l"(pb[6]) : "f"(y.z));
            asm("mov.b64 %0,{%1,%1};" : "=l"(pb[7]) : "f"(y.w));
#pragma unroll
            for (int q = 0; q < 8; q++) {
                asm("fma.rn.f32x2 %0,%1,%2,%0;" : "+l"(acc[0][q]) : "l"(pa0.x), "l"(pb[q]));
                asm("fma.rn.f32x2 %0,%1,%2,%0;" : "+l"(acc[1][q]) : "l"(pa0.y), "l"(pb[q]));
                asm("fma.rn.f32x2 %0,%1,%2,%0;" : "+l"(acc[2][q]) : "l"(pa1.x), "l"(pb[q]));
                asm("fma.rn.f32x2 %0,%1,%2,%0;" : "+l"(acc[3][q]) : "l"(pa1.y), "l"(pb[q]));
            }
        }
        if (more) {
            const int nb = buf ^ 1;
            As[nb][lac+0][lar]=a0.x; As[nb][lac+1][lar]=a0.y; As[nb][lac+2][lar]=a0.z; As[nb][lac+3][lar]=a0.w;
            As[nb][lac+4][lar]=a1.x; As[nb][lac+5][lar]=a1.y; As[nb][lac+6][lar]=a1.z; As[nb][lac+7][lar]=a1.w;
        }
        buf ^= 1;
    }

    const int gc = n0 + tn * 8;
#pragma unroll
    for (int p = 0; p < 4; p++)
#pragma unroll
    for (int h = 0; h < 2; h++) {
        const int gm = m0 + tm * 8 + p * 2 + h;
        float v[8];
#pragma unroll
        for (int q = 0; q < 8; q++) {
            float lo, hi;
            asm("mov.b64 {%0,%1},%2;" : "=f"(lo), "=f"(hi) : "l"(acc[p][q]));
            v[q] = h ? hi : lo;
        }
        epi_row(g, gm, gc, 8, v);
    }
}

// ---------------- 128x64 core (serial-chain launches: 2 blocks/SM) ----------------
__device__ __forceinline__ void gemm_core64(const GA& g,
                                            float (&As)[2][16][132],
                                            float (&Bs)[2][16][68],
                                            int bxi, int byi)
{
    const int tid = threadIdx.x;
    const int tm = tid >> 4, tn = tid & 15;
    const int m0 = byi * 128, n0 = bxi * 64;
    const int lar = tid >> 1, lac = (tid & 1) * 8;
    const int N = g.N, K = g.K;

    const float* Aload = g.A + (size_t)(m0 + lar) * g.lda + lac;
    const float* Bload = g.B + n0;
    const uint32_t bsU = s2u(&Bs[0][0][0]);
    const int br = tid >> 4, bc = (tid & 15) * 4;   // 16 rows x 16 float4

    unsigned long long acc[4][4];
#pragma unroll
    for (int p = 0; p < 4; p++)
#pragma unroll
        for (int q = 0; q < 4; q++) acc[p][q] = 0ull;

    {
        cpasync16(bsU + ((br * 68 + bc) << 2), Bload + (size_t)br * N + bc);
        CP_COMMIT();
        float4 a0 = ldgcg4(Aload);
        float4 a1 = ldgcg4(Aload + 4);
        As[0][lac+0][lar]=a0.x; As[0][lac+1][lar]=a0.y; As[0][lac+2][lar]=a0.z; As[0][lac+3][lar]=a0.w;
        As[0][lac+4][lar]=a1.x; As[0][lac+5][lar]=a1.y; As[0][lac+6][lar]=a1.z; As[0][lac+7][lar]=a1.w;
    }

    int buf = 0;
    for (int kt = 0; kt < K; kt += 16) {
        const bool more = (kt + 16) < K;
        CP_WAIT0();
        __syncthreads();
        if (more) {
            const float* Bk = Bload + (size_t)(kt + 16) * N;
            const uint32_t bb = bsU + (uint32_t)((buf ^ 1) * 16 * 68 * 4);
            cpasync16(bb + ((br * 68 + bc) << 2), Bk + (size_t)br * N + bc);
            CP_COMMIT();
        }
        float4 a0, a1;
        if (more) {
            a0 = ldgcg4(Aload + kt + 16);
            a1 = ldgcg4(Aload + kt + 20);
        }
#pragma unroll
        for (int k = 0; k < 16; k++) {
            const ulonglong2 pa0 = *(const ulonglong2*)&As[buf][k][tm * 8];
            const ulonglong2 pa1 = *(const ulonglong2*)&As[buf][k][tm * 8 + 4];
            const float4 x = *(const float4*)&Bs[buf][k][tn * 4];
            unsigned long long pb[4];
            asm("mov.b64 %0,{%1,%1};" : "=l"(pb[0]) : "f"(x.x));
            asm("mov.b64 %0,{%1,%1};" : "=l"(pb[1]) : "f"(x.y));
            asm("mov.b64 %0,{%1,%1};" : "=l"(pb[2]) : "f"(x.z));
            asm("mov.b64 %0,{%1,%1};" : "=l"(pb[3]) : "f"(x.w));
#pragma unroll
            for (int q = 0; q < 4; q++) {
                asm("fma.rn.f32x2 %0,%1,%2,%0;" : "+l"(acc[0][q]) : "l"(pa0.x), "l"(pb[q]));
                asm("fma.rn.f32x2 %0,%1,%2,%0;" : "+l"(acc[1][q]) : "l"(pa0.y), "l"(pb[q]));
                asm("fma.rn.f32x2 %0,%1,%2,%0;" : "+l"(acc[2][q]) : "l"(pa1.x), "l"(pb[q]));
                asm("fma.rn.f32x2 %0,%1,%2,%0;" : "+l"(acc[3][q]) : "l"(pa1.y), "l"(pb[q]));
            }
        }
        if (more) {
            const int nb = buf ^ 1;
            As[nb][lac+0][lar]=a0.x; As[nb][lac+1][lar]=a0.y; As[nb][lac+2][lar]=a0.z; As[nb][lac+3][lar]=a0.w;
            As[nb][lac+4][lar]=a1.x; As[nb][lac+5][lar]=a1.y; As[nb][lac+6][lar]=a1.z; As[nb][lac+7][lar]=a1.w;
        }
        buf ^= 1;
    }

    const int gc = n0 + tn * 4;
#pragma unroll
    for (int p = 0; p < 4; p++)
#pragma unroll
    for (int h = 0; h < 2; h++) {
        const int gm = m0 + tm * 8 + p * 2 + h;
        float v[4];
#pragma unroll
        for (int q = 0; q < 4; q++) {
            float lo, hi;
            asm("mov.b64 {%0,%1},%2;" : "=f"(lo), "=f"(hi) : "l"(acc[p][q]));
            v[q] = h ? hi : lo;
        }
        epi_row(g, gm, gc, 4, v);
    }
}

__global__ void __launch_bounds__(256, 2) gemm_one(GA g)
{
    __shared__ float As[2][16][132];
    __shared__ float Bs[2][16][132];
    gemm_core(g, As, Bs, blockIdx.x, blockIdx.y);
}

__global__ void __launch_bounds__(256, 2) gemm_two(GA g1, GA g2, int bySplit)
{
    __shared__ float As[2][16][132];
    __shared__ float Bs[2][16][132];
    if ((int)blockIdx.y < bySplit)
        gemm_core(g1, As, Bs, blockIdx.x, blockIdx.y);
    else
        gemm_core(g2, As, Bs, blockIdx.x, blockIdx.y - bySplit);
}

__global__ void __launch_bounds__(256, 2) gemm_one64(GA g)
{
    __shared__ float As[2][16][132];
    __shared__ float Bs[2][16][68];
    gemm_core64(g, As, Bs, blockIdx.x, blockIdx.y);
}

__global__ void __launch_bounds__(256, 2) gemm_two64(GA g1, GA g2, int bySplit)
{
    __shared__ float As[2][16][132];
    __shared__ float Bs[2][16][68];
    if ((int)blockIdx.y < bySplit)
        gemm_core64(g1, As, Bs, blockIdx.x, blockIdx.y);
    else
        gemm_core64(g2, As, Bs, blockIdx.x, blockIdx.y - bySplit);
}

// grid barrier for the persistent phase-2 kernel
__device__ __forceinline__ void gbar(int s)
{
    __syncthreads();
    __threadfence();
    if (threadIdx.x == 0) {
        atomicAdd(&g_ctr[s], 1u);
        while (*(volatile unsigned*)&g_ctr[s] < (unsigned)PBLK_) {}
    }
    __syncthreads();
}

// Persistent phase-2: 16 scan steps (n64 tiles, 256 blocks = 2/SM).
__global__ void __launch_bounds__(256, 2)
scan2(float* bufA, float* bufB, const float* Amat,
      const float* Bu, float* outH)
{
    __shared__ float As[2][16][132];
    __shared__ float Bs[2][16][68];
    const size_t AP = (size_t)APRON_ * HD_;
    const int bx = blockIdx.x & 15, by = blockIdx.x >> 4;
    float* cur = bufA;
    float* nxt = bufB;
    for (int j = 0; j < CH_; j++) {
        const float* Ain = (j == 0) ? (cur + AP - (size_t)16 * HD_) : (cur + AP);
        GA g = mkGA(Ain, HD_, Amat, nxt + AP, HD_, HD_, GF_SADD | GF_SSTORE,
                    nullptr, Bu, outH, nullptr, j);
        gemm_core64(g, As, Bs, bx, by);
        if (j < CH_ - 1) gbar(j);
        float* t = cur; cur = nxt; nxt = t;
    }
}

__global__ void zeroCtr()
{
    if (threadIdx.x < 32) g_ctr[threadIdx.x] = 0u;
}

#define SF_BIAS 1
#define SF_RELU 2
#define SF_ADD  4

template<int F>
__global__ void __launch_bounds__(256)
sgemmKS(const float* __restrict__ Ap, long lda,
        const float* __restrict__ Bp, int ldb,
        float* __restrict__ Cp, int ldc,
        const float* __restrict__ bias,
        const float* __restrict__ addend, long ldadd,
        int M, int K)
{
    __shared__ float As[4][16][33];
    __shared__ float Rs[4][16][64];
    const int tid = threadIdx.x;
    const int c = tid & 63, g = tid >> 6;
    const int col = blockIdx.x * 64 + c;
    const int kQ = K >> 2;
    float acc[16];
#pragma unroll
    for (int r = 0; r < 16; r++) acc[r] = 0.f;
    for (int k0 = 0; k0 < kQ; k0 += 32) {
        __syncthreads();
        for (int e = tid; e < 2048; e += 256) {
            const int gg = e >> 9, rem = e & 511, r = rem >> 5, kk = rem & 31;
            As[gg][r][kk] = (r < M) ? Ap[(size_t)r * lda + gg * kQ + k0 + kk] : 0.f;
        }
        __syncthreads();
#pragma unroll 8
        for (int kk = 0; kk < 32; kk++) {
            const float bv = Bp[(size_t)(g * kQ + k0 + kk) * ldb + col];
#pragma unroll
            for (int r = 0; r < 16; r++) acc[r] += As[g][r][kk] * bv;
        }
    }
    __syncthreads();
#pragma unroll
    for (int r = 0; r < 16; r++) Rs[g][r][c] = acc[r];
    __syncthreads();
    if (g == 0) {
#pragma unroll
        for (int r = 0; r < 16; r++) {
            if (r < M) {
                float v = Rs[0][r][c] + Rs[1][r][c] + Rs[2][r][c] + Rs[3][r][c];
                if (F & SF_BIAS) v += bias[col];
                if (F & SF_ADD)  v += addend[(size_t)r * ldadd + col];
                if (F & SF_RELU) v = fmaxf(v, 0.f);
                Cp[(size_t)r * ldc + col] = v;
            }
        }
    }
}

__global__ void __launch_bounds__(256)
ln16(const float* __restrict__ z, const float* __restrict__ gam,
     const float* __restrict__ bet, float* __restrict__ o)
{
    __shared__ float s1[8], s2[8];
    const int b = blockIdx.x, tid = threadIdx.x;
    float4 v = ((const float4*)(z + (size_t)b * HD_))[tid];
    float s = v.x + v.y + v.z + v.w;
    float q = v.x*v.x + v.y*v.y + v.z*v.z + v.w*v.w;
    for (int d = 16; d > 0; d >>= 1) {
        s += __shfl_xor_sync(0xffffffffu, s, d);
        q += __shfl_xor_sync(0xffffffffu, q, d);
    }
    if ((tid & 31) == 0) { s1[tid >> 5] = s; s2[tid >> 5] = q; }
    __syncthreads();
    if (tid < 8) {
        s = s1[tid]; q = s2[tid];
        for (int d = 4; d > 0; d >>= 1) {
            s += __shfl_xor_sync(0xffu, s, d);
            q += __shfl_xor_sync(0xffu, q, d);
        }
        if (tid == 0) { s1[0] = s; s2[0] = q; }
    }
    __syncthreads();
    const float mu = s1[0] * (1.f / HD_);
    const float var = s2[0] * (1.f / HD_) - mu * mu;
    const float rs = rsqrtf(var + 1e-5f);
    float4 gg = ((const float4*)gam)[tid];
    float4 bb = ((const float4*)bet)[tid];
    float4 r;
    r.x = (v.x - mu) * rs * gg.x + bb.x;
    r.y = (v.y - mu) * rs * gg.y + bb.y;
    r.z = (v.z - mu) * rs * gg.z + bb.z;
    r.w = (v.w - mu) * rs * gg.w + bb.w;
    ((float4*)(o + (size_t)b * HD_))[tid] = r;
}

// remap batch-major endpoints (row b*128+c) -> scan layout (row c*16+b)
__global__ void remapE(const float* __restrict__ s, float* __restrict__ d)
{
    const int r = blockIdx.x;
    const int b = r >> 7, c = r & 127;
    ((float4*)(d + (size_t)(c * 16 + b) * HD_))[threadIdx.x] =
        ((const float4*)(s + (size_t)r * HD_))[threadIdx.x];
}

__global__ void zero4(float* p)
{
    ((float4*)p)[(size_t)blockIdx.x * 256 + threadIdx.x] = make_float4(0.f, 0.f, 0.f, 0.f);
}

__global__ void stageWE(const float* __restrict__ Wenc,
                        const float* __restrict__ benc, float* __restrict__ S)
{
    const int r = blockIdx.x, i = threadIdx.x;
    float2 v = make_float2(0.f, 0.f);
    if (r < 256)       v = ((const float2*)(Wenc + (size_t)r * MENC_))[i];
    else if (r == 256) v = ((const float2*)benc)[i];
    ((float2*)(S + (size_t)r * MENC_))[i] = v;
}

extern "C" void kernel_launch(void* const* d_in, const int* in_sizes, int n_in,
                              void* d_out, int out_size)
{
    (void)in_sizes; (void)n_in; (void)out_size;
    const float* x    = (const float*)d_in[0];
    const float* Wenc = (const float*)d_in[1];
    const float* benc = (const float*)d_in[2];
    const float* WB   = (const float*)d_in[3];
    const float* Amat = (const float*)d_in[4];
    const float* Wres = (const float*)d_in[5];
    const float* bres = (const float*)d_in[6];
    const float* lng  = (const float*)d_in[7];
    const float* lnb  = (const float*)d_in[8];
    const float* W1   = (const float*)d_in[9];
    const float* b1   = (const float*)d_in[10];
    const float* W2   = (const float*)d_in[11];
    const float* b2   = (const float*)d_in[12];
    float* out0 = (float*)d_out;
    float* outH = out0 + BATCH_ * HD_;

    float *WE, *WxB, *Bu, *D1, *D2, *P0, *P1, *P2, *FA, *FB, *Z, *HL, *T;
    cudaGetSymbolAddress((void**)&WE,   g_WE);
    cudaGetSymbolAddress((void**)&WxB,  g_WxB);
    cudaGetSymbolAddress((void**)&Bu,   g_Bu);
    cudaGetSymbolAddress((void**)&D1,   g_D1);
    cudaGetSymbolAddress((void**)&D2,   g_D2);
    cudaGetSymbolAddress((void**)&P0,   g_P0);
    cudaGetSymbolAddress((void**)&P1,   g_P1);
    cudaGetSymbolAddress((void**)&P2,   g_P2);
    cudaGetSymbolAddress((void**)&FA,   g_FA);
    cudaGetSymbolAddress((void**)&FB,   g_FB);
    cudaGetSymbolAddress((void**)&Z,    g_Z);
    cudaGetSymbolAddress((void**)&HL,   g_HL);
    cudaGetSymbolAddress((void**)&T,    g_T);

    const size_t AP = (size_t)APRON_ * HD_;

    // 0) counters, aprons, encoder staging
    zeroCtr<<<1, 32>>>();
    zero4<<<1024, 256>>>(FA);
    zero4<<<1024, 256>>>(FB);
    stageWE<<<384, 256>>>(Wenc, benc, WE);

    // 1) [Wx; bvec] = [Wenc; benc] @ WB
    gemm_one<<<dim3(8, 3), 256>>>(mkGA(WE, MENC_, WB, WxB, HD_, MENC_, 0));

    // 2) Bu = x2d @ Wx + bvec
    gemm_one<<<dim3(8, 256), 256>>>(mkGA(x, LIN_, WxB, Bu, HD_, LIN_, GF_BIAS,
                                         WxB + (size_t)256 * HD_));

    // 3) Phase 1 by pairwise doubling (4 serial levels), squarings fused
    gemm_two<<<dim3(8, 136), 256>>>(
        mkGA(Bu, 2*HD_, Amat, D1, HD_, HD_, GF_ADDM, nullptr, nullptr, nullptr,
             Bu + HD_, 0, 2*HD_),
        mkGA(Amat, HD_, Amat, P0, HD_, HD_, 0), 128);
    gemm_two<<<dim3(8, 72), 256>>>(
        mkGA(D1, 2*HD_, P0, D2, HD_, HD_, GF_ADDM, nullptr, nullptr, nullptr,
             D1 + HD_, 0, 2*HD_),
        mkGA(P0, HD_, P0, P1, HD_, HD_, 0), 64);
    gemm_two<<<dim3(8, 40), 256>>>(
        mkGA(D2, 2*HD_, P1, D1, HD_, HD_, GF_ADDM, nullptr, nullptr, nullptr,
             D2 + HD_, 0, 2*HD_),
        mkGA(P1, HD_, P1, P2, HD_, HD_, 0), 32);
    gemm_two<<<dim3(8, 24), 256>>>(
        mkGA(D1, 2*HD_, P2, D2, HD_, HD_, GF_ADDM, nullptr, nullptr, nullptr,
             D1 + HD_, 0, 2*HD_),
        mkGA(P2, HD_, P2, P0, HD_, HD_, 0), 16);
    remapE<<<ROWS_, 256>>>(D2, FA + AP);

    // 4) Hillis-Steele prefix over 128 chunks (7 rounds) with n64 tiles:
    //    prefix segment = 256 blocks (2/SM); squaring fused as n64 segment.
    float* cur = FA; float* nxt = FB;
    float* Pk = P0; float* Po = P1;
    for (int r = 0; r < 7; r++) {
        const int s = 1 << r;
        GA pre = mkGA(cur + AP - (size_t)16 * s * HD_, HD_, Pk, nxt + AP,
                      HD_, HD_, GF_ADDM, nullptr, nullptr, nullptr, cur + AP);
        if (r < 6) {
            gemm_two64<<<dim3(16, 24), 256>>>(pre, mkGA(Pk, HD_, Pk, Po, HD_, HD_, 0), 16);
            float* u = Pk; Pk = Po; Po = u;
        } else {
            gemm_one64<<<dim3(16, 16), 256>>>(pre);
        }
        float* t = cur; cur = nxt; nxt = t;
    }

    // 5) Phase 2: persistent 16-step scan (n64, 256 blocks, grid barriers)
    scan2<<<PBLK_, 256>>>(cur, nxt, Amat, Bu, outH);

    // 6) tail
    sgemmKS<SF_BIAS | SF_ADD><<<16, 256>>>(x + (size_t)(SEQ_ - 1) * LIN_,
                                           (long)SEQ_ * LIN_,
                                           Wres, HD_, Z, HD_, bres,
                                           outH + (size_t)(SEQ_ - 1) * HD_,
                                           (long)SEQ_ * HD_, BATCH_, LIN_);
    ln16<<<BATCH_, 256>>>(Z, lng, lnb, HL);
    sgemmKS<SF_BIAS | SF_RELU><<<FMLP_ / 64, 256>>>(HL, HD_, W1, FMLP_, T, FMLP_,
                                                    b1, nullptr, 0, BATCH_, HD_);
    sgemmKS<SF_BIAS><<<HD_ / 64, 256>>>(T, FMLP_, W2, HD_, out0, HD_,
                                        b2, nullptr, 0, BATCH_, FMLP_);
}